// round 3
// baseline (speedup 1.0000x reference)
#include <cuda_runtime.h>

#define BB   16
#define HH   64
#define WW   64
#define CIN  256
#define COUT 256

// demod scale d[b, co] = rsqrt(sum_{kh,kw,ci} (kernel * (style+1))^2 + 1e-8)
__device__ float g_demod[BB * COUT];

__global__ __launch_bounds__(256)
void demod_kernel(const float* __restrict__ style, const float* __restrict__ kern) {
    int b  = blockIdx.x;
    int co = threadIdx.x;  // 256 threads == COUT
    __shared__ float s2[CIN];
    float s = style[b * CIN + threadIdx.x] + 1.0f;
    s2[threadIdx.x] = s * s;
    __syncthreads();

    float acc = 0.0f;
    #pragma unroll 1
    for (int t = 0; t < 9; ++t) {
        const float* kp = kern + (size_t)t * CIN * COUT + co;
        #pragma unroll 8
        for (int ci = 0; ci < CIN; ++ci) {
            float k = kp[(size_t)ci * COUT];
            acc += s2[ci] * k * k;
        }
    }
    g_demod[b * COUT + co] = rsqrtf(acc + 1e-8f);
}

// Main conv: per block = (b, 8x8 pixel tile [M=64], 64 couts [N=64]).
// K loop: 9 taps x 8 chunks of 32 input channels.
// As[m][k] (padded rows, conflict-free ci-minor stores), Bs[k][n] (float4 reads).
__global__ __launch_bounds__(256)
void modconv_kernel(const float* __restrict__ x,
                    const float* __restrict__ style,
                    const float* __restrict__ kern,
                    float* __restrict__ out) {
    __shared__ float As[64][33];   // [pixel][k-chunk], +1 pad
    __shared__ float Bs[32][64];   // [k-chunk][cout]
    __shared__ float smod[CIN];    // style + 1

    const int b    = blockIdx.z;
    const int tile = blockIdx.y;          // 0..63  (8x8 tiles of 8x8 pixels)
    const int n0   = blockIdx.x * 64;     // cout tile base

    const int ty0 = (tile >> 3) * 8;      // tile row origin
    const int tx0 = (tile & 7) * 8;       // tile col origin

    const int tid = threadIdx.x;
    smod[tid] = style[b * CIN + tid] + 1.0f;   // 256 threads == CIN

    const int tn = tid & 15;   // n micro index (x4)
    const int tm = tid >> 4;   // m micro index (x4)

    float acc[4][4];
    #pragma unroll
    for (int i = 0; i < 4; ++i)
        #pragma unroll
        for (int j = 0; j < 4; ++j) acc[i][j] = 0.0f;

    const float* xb = x + (size_t)b * HH * WW * CIN;

    #pragma unroll 1
    for (int kh = 0; kh < 3; ++kh) {
        #pragma unroll 1
        for (int kw = 0; kw < 3; ++kw) {
            const float* kslice = kern + (size_t)(kh * 3 + kw) * CIN * COUT;
            #pragma unroll 1
            for (int c0 = 0; c0 < CIN; c0 += 32) {
                __syncthreads();   // previous tile fully consumed (also covers smod on iter 0)

                // ---- load B tile: 32 k x 64 n, coalesced over n ----
                #pragma unroll
                for (int r = 0; r < 8; ++r) {
                    int idx = tid + r * 256;      // 0..2047
                    int kc  = idx >> 6;
                    int n   = idx & 63;
                    Bs[kc][n] = kslice[(size_t)(c0 + kc) * COUT + n0 + n];
                }

                // ---- load A tile: 64 pixels x 32 ci, ci-minor (coalesced) ----
                #pragma unroll
                for (int r = 0; r < 8; ++r) {
                    int idx  = tid + r * 256;     // 0..2047
                    int p    = idx >> 5;          // pixel 0..63
                    int kc   = idx & 31;
                    int prow = p >> 3;
                    int pcol = p & 7;
                    int gy = ty0 + prow + kh - 1;
                    int gx = tx0 + pcol + kw - 1;
                    float v = 0.0f;
                    if ((unsigned)gy < (unsigned)HH && (unsigned)gx < (unsigned)WW)
                        v = xb[((size_t)gy * WW + gx) * CIN + c0 + kc] * smod[c0 + kc];
                    As[p][kc] = v;
                }
                __syncthreads();

                // ---- 64x64x32 GEMM fragment, 4x4 per thread ----
                #pragma unroll
                for (int kc = 0; kc < 32; ++kc) {
                    float a0 = As[tm * 4 + 0][kc];
                    float a1 = As[tm * 4 + 1][kc];
                    float a2 = As[tm * 4 + 2][kc];
                    float a3 = As[tm * 4 + 3][kc];
                    float4 bv = *(const float4*)&Bs[kc][tn * 4];
                    acc[0][0] += a0 * bv.x; acc[0][1] += a0 * bv.y;
                    acc[0][2] += a0 * bv.z; acc[0][3] += a0 * bv.w;
                    acc[1][0] += a1 * bv.x; acc[1][1] += a1 * bv.y;
                    acc[1][2] += a1 * bv.z; acc[1][3] += a1 * bv.w;
                    acc[2][0] += a2 * bv.x; acc[2][1] += a2 * bv.y;
                    acc[2][2] += a2 * bv.z; acc[2][3] += a2 * bv.w;
                    acc[3][0] += a3 * bv.x; acc[3][1] += a3 * bv.y;
                    acc[3][2] += a3 * bv.z; acc[3][3] += a3 * bv.w;
                }
            }
        }
    }

    // ---- epilogue: demodulate + store ----
    const float* dmp = &g_demod[b * COUT + n0 + tn * 4];
    float d0 = dmp[0], d1 = dmp[1], d2 = dmp[2], d3 = dmp[3];

    #pragma unroll
    for (int i = 0; i < 4; ++i) {
        int p    = tm * 4 + i;
        int prow = p >> 3;
        int pcol = p & 7;
        int gy = ty0 + prow;
        int gx = tx0 + pcol;
        float4 o;
        o.x = acc[i][0] * d0;
        o.y = acc[i][1] * d1;
        o.z = acc[i][2] * d2;
        o.w = acc[i][3] * d3;
        *(float4*)(out + (((size_t)b * HH + gy) * WW + gx) * COUT + n0 + tn * 4) = o;
    }
}

extern "C" void kernel_launch(void* const* d_in, const int* in_sizes, int n_in,
                              void* d_out, int out_size) {
    const float* x     = (const float*)d_in[0];  // [16,64,64,256]
    const float* style = (const float*)d_in[1];  // [16,256]
    const float* kern  = (const float*)d_in[2];  // [3,3,256,256]
    float* out = (float*)d_out;                  // [16,64,64,256]

    demod_kernel<<<BB, 256>>>(style, kern);

    dim3 grid(COUT / 64, (HH / 8) * (WW / 8), BB);  // (4, 64, 16)
    modconv_kernel<<<grid, 256>>>(x, style, kern, out);
}

// round 6
// speedup vs baseline: 2.9305x; 2.9305x over previous
#include <cuda_runtime.h>
#include <cuda_bf16.h>
#include <cstdint>

#define BB   16
#define HH   64
#define WW   64
#define CIN  256
#define COUT 256

// ---------------- device scratch (static, no allocs) ----------------
__device__ float g_demod[BB * COUT];
__device__ __nv_bfloat16 g_w_hi[9 * COUT * CIN];              // [tap][co][ci]
__device__ __nv_bfloat16 g_w_lo[9 * COUT * CIN];
__device__ __nv_bfloat16 g_xm_hi[BB * HH * WW * CIN];         // [b][y][x][ci]
__device__ __nv_bfloat16 g_xm_lo[BB * HH * WW * CIN];

// ---------------- helpers ----------------
__device__ __forceinline__ uint32_t smem_u32(const void* p) {
    uint32_t a;
    asm("{ .reg .u64 t; cvta.to.shared.u64 t, %1; cvt.u32.u64 %0, t; }" : "=r"(a) : "l"(p));
    return a;
}
__device__ __forceinline__ uint32_t sw128(uint32_t off) { return off ^ ((off >> 3) & 0x70); }

__device__ __forceinline__ void cp16(uint32_t dst, const void* src, uint32_t sz) {
    asm volatile("cp.async.cg.shared.global [%0], [%1], 16, %2;"
                 :: "r"(dst), "l"(src), "r"(sz) : "memory");
}
#define CP_COMMIT() asm volatile("cp.async.commit_group;" ::: "memory")
#define CP_WAIT1()  asm volatile("cp.async.wait_group 1;" ::: "memory")
#define CP_WAIT0()  asm volatile("cp.async.wait_group 0;" ::: "memory")

__device__ __forceinline__ void ldsm4(uint32_t* r, uint32_t addr) {
    asm volatile("ldmatrix.sync.aligned.m8n8.x4.shared.b16 {%0,%1,%2,%3}, [%4];"
                 : "=r"(r[0]), "=r"(r[1]), "=r"(r[2]), "=r"(r[3]) : "r"(addr));
}
#define MMA(d, a, b)                                                         \
    asm volatile("mma.sync.aligned.m16n8k16.row.col.f32.bf16.bf16.f32 "      \
        "{%0,%1,%2,%3}, {%4,%5,%6,%7}, {%8,%9}, {%0,%1,%2,%3};"              \
        : "+f"((d)[0]), "+f"((d)[1]), "+f"((d)[2]), "+f"((d)[3])             \
        : "r"((a)[0]), "r"((a)[1]), "r"((a)[2]), "r"((a)[3]),                \
          "r"((b)[0]), "r"((b)[1]))

// ---------------- prep kernels ----------------
__global__ __launch_bounds__(256)
void demod_kernel(const float* __restrict__ style, const float* __restrict__ kern) {
    int b = blockIdx.x, co = threadIdx.x;
    __shared__ float s2[CIN];
    float s = style[b * CIN + threadIdx.x] + 1.0f;
    s2[threadIdx.x] = s * s;
    __syncthreads();
    float acc = 0.0f;
    #pragma unroll 1
    for (int t = 0; t < 9; ++t) {
        const float* kp = kern + (size_t)t * CIN * COUT + co;
        #pragma unroll 8
        for (int ci = 0; ci < CIN; ++ci) {
            float k = kp[(size_t)ci * COUT];
            acc += s2[ci] * k * k;
        }
    }
    g_demod[b * COUT + co] = rsqrtf(acc + 1e-8f);
}

// W[t][ci][co] fp32 -> W_hi/lo[t][co][ci] bf16
__global__ __launch_bounds__(256)
void wprep_kernel(const float* __restrict__ kern) {
    int t = blockIdx.x >> 8, co = blockIdx.x & 255, ci = threadIdx.x;
    float v = kern[((size_t)t * CIN + ci) * COUT + co];
    __nv_bfloat16 h = __float2bfloat16(v);
    float lo = v - __bfloat162float(h);
    size_t o = ((size_t)t * COUT + co) * CIN + ci;
    g_w_hi[o] = h;
    g_w_lo[o] = __float2bfloat16(lo);
}

// x * (style+1) -> bf16 hi/lo
__global__ __launch_bounds__(256)
void xprep_kernel(const float* __restrict__ x, const float* __restrict__ style) {
    __shared__ float sm[CIN];
    int b = blockIdx.y;
    sm[threadIdx.x] = style[b * CIN + threadIdx.x] + 1.0f;
    __syncthreads();
    int i = blockIdx.x * 256 + threadIdx.x;
    size_t base = (size_t)b * (HH * WW * CIN) + (size_t)i * 4;
    float4 v = *(const float4*)(x + base);
    int ci = (i * 4) & 255;
    v.x *= sm[ci]; v.y *= sm[ci + 1]; v.z *= sm[ci + 2]; v.w *= sm[ci + 3];
    __nv_bfloat16 h0 = __float2bfloat16(v.x), h1 = __float2bfloat16(v.y),
                  h2 = __float2bfloat16(v.z), h3 = __float2bfloat16(v.w);
    __nv_bfloat16 l0 = __float2bfloat16(v.x - __bfloat162float(h0));
    __nv_bfloat16 l1 = __float2bfloat16(v.y - __bfloat162float(h1));
    __nv_bfloat16 l2 = __float2bfloat16(v.z - __bfloat162float(h2));
    __nv_bfloat16 l3 = __float2bfloat16(v.w - __bfloat162float(h3));
    ushort4 hv, lv;
    hv.x = *(unsigned short*)&h0; hv.y = *(unsigned short*)&h1;
    hv.z = *(unsigned short*)&h2; hv.w = *(unsigned short*)&h3;
    lv.x = *(unsigned short*)&l0; lv.y = *(unsigned short*)&l1;
    lv.z = *(unsigned short*)&l2; lv.w = *(unsigned short*)&l3;
    *(ushort4*)(g_xm_hi + base) = hv;
    *(ushort4*)(g_xm_lo + base) = lv;
}

// ---------------- main HMMA kernel ----------------
// CTA: 128 pixels (2 rows) x 128 couts. K = 9 taps x 4 chunks of 64 ci = 36 stages.
// Stage smem: A_hi 16K | A_lo 16K | B_hi 16K | B_lo 16K  = 64KB, double buffered.
#define ST_AH 0
#define ST_AL 16384
#define ST_BH 32768
#define ST_BL 49152
#define ST_SZ 65536
#define SMEM_TOTAL (2 * ST_SZ)

struct Frag { uint32_t r[4]; };

__global__ __launch_bounds__(256, 1)
void modconv_hmma_kernel(float* __restrict__ out) {
    extern __shared__ __align__(1024) char smem[];
    const uint32_t sb = smem_u32(smem);
    const int tid = threadIdx.x;
    const int wid = tid >> 5;
    const int lid = tid & 31;

    const int mtile = blockIdx.x;            // 0..511
    const int b  = mtile >> 5;
    const int y0 = (mtile & 31) * 2;
    const int n0 = blockIdx.y * 128;

    const int warp_m = wid & 1;              // 2 x 64 rows
    const int warp_n = wid >> 1;             // 4 x 32 couts

    const __nv_bfloat16* xh = g_xm_hi + (size_t)b * (HH * WW * CIN);
    const __nv_bfloat16* xl = g_xm_lo + (size_t)b * (HH * WW * CIN);

    float acc[4][4][4];
    #pragma unroll
    for (int mi = 0; mi < 4; ++mi)
        #pragma unroll
        for (int g = 0; g < 4; ++g)
            #pragma unroll
            for (int q = 0; q < 4; ++q) acc[mi][g][q] = 0.0f;

    // ---- stage loader ----
    auto load_stage = [&](int s, int buf) {
        const int t  = s >> 2;
        const int c0 = (s & 3) * 64;
        const int dy = t / 3 - 1;
        const int dx = t % 3 - 1;
        const uint32_t stage = sb + buf * ST_SZ;
        const __nv_bfloat16* wh = g_w_hi + (size_t)t * COUT * CIN;
        const __nv_bfloat16* wl = g_w_lo + (size_t)t * COUT * CIN;

        #pragma unroll
        for (int i = 0; i < 4; ++i) {
            int u   = tid + i * 256;          // 0..1023
            int p   = u >> 3;
            int seg = u & 7;
            int gy  = y0 + (p >> 6) + dy;
            int gx  = (p & 63) + dx;
            bool ok = ((unsigned)gy < (unsigned)HH) && ((unsigned)gx < (unsigned)WW);
            int cy = ok ? gy : 0, cx = ok ? gx : 0;
            size_t go = ((size_t)(cy * WW + cx)) * CIN + c0 + seg * 8;
            uint32_t sw = sw128((uint32_t)(p * 128 + seg * 16));
            uint32_t sz = ok ? 16u : 0u;
            cp16(stage + ST_AH + sw, xh + go, sz);
            cp16(stage + ST_AL + sw, xl + go, sz);
        }
        #pragma unroll
        for (int i = 0; i < 4; ++i) {
            int u   = tid + i * 256;
            int co  = u >> 3;
            int seg = u & 7;
            size_t go = (size_t)(n0 + co) * CIN + c0 + seg * 8;
            uint32_t sw = sw128((uint32_t)(co * 128 + seg * 16));
            cp16(stage + ST_BH + sw, wh + go, 16u);
            cp16(stage + ST_BL + sw, wl + go, 16u);
        }
    };

    // ---- ldmatrix lane addressing (precompute invariant parts) ----
    const int a_row_base = warp_m * 64 + (lid & 15);     // + mi*16
    const int a_col_half = (lid >> 4) << 3;              // + kk*16  (bf16 cols)
    const int b_row_base = warp_n * 32 + ((lid >> 4) << 3) + (lid & 7);   // + h*16
    const int b_col_half = ((lid >> 3) & 1) << 3;        // + kk*16

    load_stage(0, 0);
    CP_COMMIT();

    #pragma unroll 1
    for (int s = 0; s < 36; ++s) {
        const int buf = s & 1;
        __syncthreads();                       // buf^1 readers done
        if (s < 35) {
            load_stage(s + 1, buf ^ 1);
            CP_COMMIT();
            CP_WAIT1();
        } else {
            CP_WAIT0();
        }
        __syncthreads();                       // stage s visible to all

        const uint32_t stg = sb + buf * ST_SZ;
        #pragma unroll
        for (int kk = 0; kk < 4; ++kk) {
            Frag ah[4], al[4];
            #pragma unroll
            for (int mi = 0; mi < 4; ++mi) {
                uint32_t off = (uint32_t)((a_row_base + mi * 16) * 128 +
                                          (kk * 16 + a_col_half) * 2);
                uint32_t sw = sw128(off);
                ldsm4(ah[mi].r, stg + ST_AH + sw);
                ldsm4(al[mi].r, stg + ST_AL + sw);
            }
            uint32_t bh[4][2], bl[4][2];
            #pragma unroll
            for (int h = 0; h < 2; ++h) {
                uint32_t off = (uint32_t)((b_row_base + h * 16) * 128 +
                                          (kk * 16) * 2 + b_col_half * 2);
                uint32_t sw = sw128(off);
                uint32_t r[4];
                ldsm4(r, stg + ST_BH + sw);
                bh[h * 2][0] = r[0]; bh[h * 2][1] = r[1];
                bh[h * 2 + 1][0] = r[2]; bh[h * 2 + 1][1] = r[3];
                ldsm4(r, stg + ST_BL + sw);
                bl[h * 2][0] = r[0]; bl[h * 2][1] = r[1];
                bl[h * 2 + 1][0] = r[2]; bl[h * 2 + 1][1] = r[3];
            }
            #pragma unroll
            for (int mi = 0; mi < 4; ++mi)
                #pragma unroll
                for (int g = 0; g < 4; ++g) {
                    MMA(acc[mi][g], ah[mi].r, bh[g]);
                    MMA(acc[mi][g], ah[mi].r, bl[g]);
                    MMA(acc[mi][g], al[mi].r, bh[g]);
                }
        }
    }

    // ---- epilogue: demodulate + store ----
    const int qrow = lid >> 2;
    const int qcol = lid & 3;
    #pragma unroll
    for (int g = 0; g < 4; ++g) {
        int c = n0 + warp_n * 32 + g * 8 + qcol * 2;
        float dm0 = g_demod[b * COUT + c];
        float dm1 = g_demod[b * COUT + c + 1];
        #pragma unroll
        for (int mi = 0; mi < 4; ++mi) {
            int p0 = warp_m * 64 + mi * 16 + qrow;
            #pragma unroll
            for (int half = 0; half < 2; ++half) {
                int p = p0 + half * 8;
                int y = y0 + (p >> 6);
                int xq = p & 63;
                float2 v;
                v.x = acc[mi][g][half * 2 + 0] * dm0;
                v.y = acc[mi][g][half * 2 + 1] * dm1;
                *(float2*)(out + (((size_t)(b * HH + y)) * WW + xq) * COUT + c) = v;
            }
        }
    }
}

// ---------------- launch ----------------
extern "C" void kernel_launch(void* const* d_in, const int* in_sizes, int n_in,
                              void* d_out, int out_size) {
    const float* x     = (const float*)d_in[0];  // [16,64,64,256]
    const float* style = (const float*)d_in[1];  // [16,256]
    const float* kern  = (const float*)d_in[2];  // [3,3,256,256]
    float* out = (float*)d_out;                  // [16,64,64,256]

    cudaFuncSetAttribute(modconv_hmma_kernel,
                         cudaFuncAttributeMaxDynamicSharedMemorySize, SMEM_TOTAL);

    demod_kernel<<<BB, 256>>>(style, kern);
    wprep_kernel<<<9 * COUT, 256>>>(kern);
    xprep_kernel<<<dim3((HH * WW * CIN) / (4 * 256), BB), 256>>>(x, style);

    modconv_hmma_kernel<<<dim3(512, 2), 256, SMEM_TOTAL>>>(out);
}

// round 8
// speedup vs baseline: 4.7509x; 1.6212x over previous
#include <cuda_runtime.h>
#include <cuda_fp16.h>
#include <cstdint>

#define BB   16
#define HH   64
#define WW   64
#define CIN  256
#define COUT 256

// ---------------- device scratch (static, no allocs) ----------------
__device__ float  g_dsum[BB * COUT];                 // sum of (k*(s+1))^2
__device__ __half g_w_h[9 * COUT * CIN];             // [tap][co][ci] fp16
__device__ __half g_xm_hi[BB * HH * WW * CIN];       // [b][y][x][ci]
__device__ __half g_xm_lo[BB * HH * WW * CIN];

// ---------------- helpers ----------------
__device__ __forceinline__ uint32_t smem_u32(const void* p) {
    uint32_t a;
    asm("{ .reg .u64 t; cvta.to.shared.u64 t, %1; cvt.u32.u64 %0, t; }" : "=r"(a) : "l"(p));
    return a;
}
__device__ __forceinline__ uint32_t sw128(uint32_t off) { return off ^ ((off >> 3) & 0x70); }

__device__ __forceinline__ void cp16(uint32_t dst, const void* src, uint32_t sz) {
    asm volatile("cp.async.cg.shared.global [%0], [%1], 16, %2;"
                 :: "r"(dst), "l"(src), "r"(sz) : "memory");
}
#define CP_COMMIT() asm volatile("cp.async.commit_group;" ::: "memory")
#define CP_WAIT2()  asm volatile("cp.async.wait_group 2;" ::: "memory")
#define CP_WAIT1()  asm volatile("cp.async.wait_group 1;" ::: "memory")
#define CP_WAIT0()  asm volatile("cp.async.wait_group 0;" ::: "memory")

__device__ __forceinline__ void ldsm4(uint32_t* r, uint32_t addr) {
    asm volatile("ldmatrix.sync.aligned.m8n8.x4.shared.b16 {%0,%1,%2,%3}, [%4];"
                 : "=r"(r[0]), "=r"(r[1]), "=r"(r[2]), "=r"(r[3]) : "r"(addr));
}
#define MMA(d, a, b)                                                         \
    asm volatile("mma.sync.aligned.m16n8k16.row.col.f32.f16.f16.f32 "        \
        "{%0,%1,%2,%3}, {%4,%5,%6,%7}, {%8,%9}, {%0,%1,%2,%3};"              \
        : "+f"((d)[0]), "+f"((d)[1]), "+f"((d)[2]), "+f"((d)[3])             \
        : "r"((a)[0]), "r"((a)[1]), "r"((a)[2]), "r"((a)[3]),                \
          "r"((b)[0]), "r"((b)[1]))

// ---------------- prep kernels ----------------
__global__ __launch_bounds__(256)
void zero_dsum_kernel() {
    g_dsum[blockIdx.x * 256 + threadIdx.x] = 0.0f;
}

// Partial demod sums: block (b, tap); 256 threads = couts; loop over 256 ci.
__global__ __launch_bounds__(256)
void demod_partial_kernel(const float* __restrict__ style, const float* __restrict__ kern) {
    const int b = blockIdx.x, t = blockIdx.y;
    const int co = threadIdx.x;
    __shared__ float s2[CIN];
    float s = style[b * CIN + threadIdx.x] + 1.0f;
    s2[threadIdx.x] = s * s;
    __syncthreads();
    float acc = 0.0f;
    const float* kp = kern + (size_t)t * CIN * COUT + co;
    #pragma unroll 8
    for (int ci = 0; ci < CIN; ++ci) {
        float k = kp[(size_t)ci * COUT];
        acc += s2[ci] * k * k;
    }
    atomicAdd(&g_dsum[b * COUT + co], acc);
}

// W[t][ci][co] fp32 -> W[t][co][ci] fp16, tiled transpose (coalesced both sides)
__global__ __launch_bounds__(256)
void wprep_kernel(const float* __restrict__ kern) {
    __shared__ float tile[32][33];
    const int t   = blockIdx.x;
    const int co0 = blockIdx.y * 32;
    const int ci0 = blockIdx.z * 32;
    const int tx = threadIdx.x & 31, ty = threadIdx.x >> 5;   // 32 x 8
    #pragma unroll
    for (int r = 0; r < 4; ++r) {
        int ci = ci0 + ty + r * 8;
        tile[ty + r * 8][tx] = kern[((size_t)t * CIN + ci) * COUT + co0 + tx];
    }
    __syncthreads();
    #pragma unroll
    for (int r = 0; r < 4; ++r) {
        int co = co0 + ty + r * 8;
        g_w_h[((size_t)t * COUT + co) * CIN + ci0 + tx] =
            __float2half_rn(tile[tx][ty + r * 8]);
    }
}

// x * (style+1) -> fp16 hi/lo
__global__ __launch_bounds__(256)
void xprep_kernel(const float* __restrict__ x, const float* __restrict__ style) {
    __shared__ float sm[CIN];
    int b = blockIdx.y;
    sm[threadIdx.x] = style[b * CIN + threadIdx.x] + 1.0f;
    __syncthreads();
    int i = blockIdx.x * 256 + threadIdx.x;
    size_t base = (size_t)b * (HH * WW * CIN) + (size_t)i * 4;
    float4 v = *(const float4*)(x + base);
    int ci = (i * 4) & 255;
    v.x *= sm[ci]; v.y *= sm[ci + 1]; v.z *= sm[ci + 2]; v.w *= sm[ci + 3];
    __half h0 = __float2half_rn(v.x), h1 = __float2half_rn(v.y),
           h2 = __float2half_rn(v.z), h3 = __float2half_rn(v.w);
    __half l0 = __float2half_rn(v.x - __half2float(h0));
    __half l1 = __float2half_rn(v.y - __half2float(h1));
    __half l2 = __float2half_rn(v.z - __half2float(h2));
    __half l3 = __float2half_rn(v.w - __half2float(h3));
    ushort4 hv, lv;
    hv.x = *(unsigned short*)&h0; hv.y = *(unsigned short*)&h1;
    hv.z = *(unsigned short*)&h2; hv.w = *(unsigned short*)&h3;
    lv.x = *(unsigned short*)&l0; lv.y = *(unsigned short*)&l1;
    lv.z = *(unsigned short*)&l2; lv.w = *(unsigned short*)&l3;
    *(ushort4*)(g_xm_hi + base) = hv;
    *(ushort4*)(g_xm_lo + base) = lv;
}

// ---------------- main HMMA kernel ----------------
// CTA: 128 pixels (2 rows) x 128 couts. K = 9 taps x 4 chunks of 64 ci = 36 stages.
// Stage: A_hi 16K | A_lo 16K | B 16K = 48KB. 4-stage ring, 1 sync per stage.
#define ST_AH 0
#define ST_AL 16384
#define ST_B  32768
#define ST_SZ 49152
#define NSTG  4
#define SMEM_TOTAL (NSTG * ST_SZ)

struct Frag { uint32_t r[4]; };

__global__ __launch_bounds__(256, 1)
void modconv_hmma_kernel(float* __restrict__ out) {
    extern __shared__ __align__(1024) char smem[];
    const uint32_t sb = smem_u32(smem);
    const int tid = threadIdx.x;
    const int wid = tid >> 5;
    const int lid = tid & 31;

    const int mtile = blockIdx.x;            // 0..511
    const int b  = mtile >> 5;
    const int y0 = (mtile & 31) * 2;
    const int n0 = blockIdx.y * 128;

    const int warp_m = wid & 1;              // 2 x 64 rows
    const int warp_n = wid >> 1;             // 4 x 32 couts

    const __half* xh = g_xm_hi + (size_t)b * (HH * WW * CIN);
    const __half* xl = g_xm_lo + (size_t)b * (HH * WW * CIN);

    float acc[4][4][4];
    #pragma unroll
    for (int mi = 0; mi < 4; ++mi)
        #pragma unroll
        for (int g = 0; g < 4; ++g)
            #pragma unroll
            for (int q = 0; q < 4; ++q) acc[mi][g][q] = 0.0f;

    auto load_stage = [&](int s) {
        const int t  = s >> 2;
        const int c0 = (s & 3) * 64;
        const int dy = t / 3 - 1;
        const int dx = t % 3 - 1;
        const uint32_t stage = sb + (s & (NSTG - 1)) * ST_SZ;
        const __half* wb = g_w_h + (size_t)t * COUT * CIN;

        #pragma unroll
        for (int i = 0; i < 4; ++i) {
            int u   = tid + i * 256;          // 0..1023
            int p   = u >> 3;
            int seg = u & 7;
            int gy  = y0 + (p >> 6) + dy;
            int gx  = (p & 63) + dx;
            bool ok = ((unsigned)gy < (unsigned)HH) && ((unsigned)gx < (unsigned)WW);
            int cy = ok ? gy : 0, cx = ok ? gx : 0;
            size_t go = ((size_t)(cy * WW + cx)) * CIN + c0 + seg * 8;
            uint32_t sw = sw128((uint32_t)(p * 128 + seg * 16));
            uint32_t sz = ok ? 16u : 0u;
            cp16(stage + ST_AH + sw, xh + go, sz);
            cp16(stage + ST_AL + sw, xl + go, sz);
        }
        #pragma unroll
        for (int i = 0; i < 4; ++i) {
            int u   = tid + i * 256;
            int co  = u >> 3;
            int seg = u & 7;
            size_t go = (size_t)(n0 + co) * CIN + c0 + seg * 8;
            uint32_t sw = sw128((uint32_t)(co * 128 + seg * 16));
            cp16(stage + ST_B + sw, wb + go, 16u);
        }
    };

    // ldmatrix lane addressing
    const int a_row_base = warp_m * 64 + (lid & 15);               // + mi*16
    const int a_col_half = (lid >> 4) << 3;                        // + kk*16
    const int b_row_base = warp_n * 32 + ((lid >> 4) << 3) + (lid & 7);  // + h*16
    const int b_col_half = ((lid >> 3) & 1) << 3;

    load_stage(0); CP_COMMIT();
    load_stage(1); CP_COMMIT();
    load_stage(2); CP_COMMIT();

    #pragma unroll 1
    for (int s = 0; s < 36; ++s) {
        if (s < 34)      CP_WAIT2();
        else if (s == 34) CP_WAIT1();
        else              CP_WAIT0();
        __syncthreads();                       // stage s visible; stage s-1 fully consumed
        if (s + 3 < 36) { load_stage(s + 3); CP_COMMIT(); }

        const uint32_t stg = sb + (s & (NSTG - 1)) * ST_SZ;
        #pragma unroll
        for (int kk = 0; kk < 4; ++kk) {
            Frag ah[4], al[4];
            #pragma unroll
            for (int mi = 0; mi < 4; ++mi) {
                uint32_t off = (uint32_t)((a_row_base + mi * 16) * 128 +
                                          (kk * 16 + a_col_half) * 2);
                uint32_t sw = sw128(off);
                ldsm4(ah[mi].r, stg + ST_AH + sw);
                ldsm4(al[mi].r, stg + ST_AL + sw);
            }
            uint32_t bf[4][2];
            #pragma unroll
            for (int h = 0; h < 2; ++h) {
                uint32_t off = (uint32_t)((b_row_base + h * 16) * 128 +
                                          (kk * 16) * 2 + b_col_half * 2);
                uint32_t sw = sw128(off);
                uint32_t r[4];
                ldsm4(r, stg + ST_B + sw);
                bf[h * 2][0] = r[0]; bf[h * 2][1] = r[1];
                bf[h * 2 + 1][0] = r[2]; bf[h * 2 + 1][1] = r[3];
            }
            #pragma unroll
            for (int mi = 0; mi < 4; ++mi)
                #pragma unroll
                for (int g = 0; g < 4; ++g) {
                    MMA(acc[mi][g], ah[mi].r, bf[g]);
                    MMA(acc[mi][g], al[mi].r, bf[g]);
                }
        }
    }

    // ---- epilogue: demodulate (rsqrt of partial sums) + store ----
    const int qrow = lid >> 2;
    const int qcol = lid & 3;
    #pragma unroll
    for (int g = 0; g < 4; ++g) {
        int c = n0 + warp_n * 32 + g * 8 + qcol * 2;
        float dm0 = rsqrtf(g_dsum[b * COUT + c] + 1e-8f);
        float dm1 = rsqrtf(g_dsum[b * COUT + c + 1] + 1e-8f);
        #pragma unroll
        for (int mi = 0; mi < 4; ++mi) {
            int p0 = warp_m * 64 + mi * 16 + qrow;
            #pragma unroll
            for (int half = 0; half < 2; ++half) {
                int p = p0 + half * 8;
                int y = y0 + (p >> 6);
                int xq = p & 63;
                float2 v;
                v.x = acc[mi][g][half * 2 + 0] * dm0;
                v.y = acc[mi][g][half * 2 + 1] * dm1;
                *(float2*)(out + (((size_t)(b * HH + y)) * WW + xq) * COUT + c) = v;
            }
        }
    }
}

// ---------------- launch ----------------
extern "C" void kernel_launch(void* const* d_in, const int* in_sizes, int n_in,
                              void* d_out, int out_size) {
    const float* x     = (const float*)d_in[0];  // [16,64,64,256]
    const float* style = (const float*)d_in[1];  // [16,256]
    const float* kern  = (const float*)d_in[2];  // [3,3,256,256]
    float* out = (float*)d_out;                  // [16,64,64,256]

    cudaFuncSetAttribute(modconv_hmma_kernel,
                         cudaFuncAttributeMaxDynamicSharedMemorySize, SMEM_TOTAL);

    zero_dsum_kernel<<<BB, 256>>>();
    demod_partial_kernel<<<dim3(BB, 9), 256>>>(style, kern);
    wprep_kernel<<<dim3(9, COUT / 32, CIN / 32), 256>>>(kern);
    xprep_kernel<<<dim3((HH * WW * CIN) / (4 * 256), BB), 256>>>(x, style);

    modconv_hmma_kernel<<<dim3(512, 2), 256, SMEM_TOTAL>>>(out);
}

// round 9
// speedup vs baseline: 8.7426x; 1.8402x over previous
#include <cuda_runtime.h>
#include <cuda_fp16.h>
#include <cstdint>

#define BB   16
#define HH   64
#define WW   64
#define CIN  256
#define COUT 256

// ---------------- device scratch (static, no allocs) ----------------
__device__ float  g_dsum[BB * COUT];                 // sum of (k*(s+1))^2
__device__ __half g_w_h[9 * COUT * CIN];             // [tap][co][ci] fp16
__device__ __half g_xm[BB * HH * WW * CIN];          // [b][y][x][ci] fp16 modulated x

// ---------------- helpers ----------------
__device__ __forceinline__ uint32_t smem_u32(const void* p) {
    uint32_t a;
    asm("{ .reg .u64 t; cvta.to.shared.u64 t, %1; cvt.u32.u64 %0, t; }" : "=r"(a) : "l"(p));
    return a;
}
__device__ __forceinline__ uint32_t sw128(uint32_t off) { return off ^ ((off >> 3) & 0x70); }

__device__ __forceinline__ void cp16(uint32_t dst, const void* src, uint32_t sz) {
    asm volatile("cp.async.cg.shared.global [%0], [%1], 16, %2;"
                 :: "r"(dst), "l"(src), "r"(sz) : "memory");
}
#define CP_COMMIT() asm volatile("cp.async.commit_group;" ::: "memory")
#define CP_WAIT1()  asm volatile("cp.async.wait_group 1;" ::: "memory")
#define CP_WAIT0()  asm volatile("cp.async.wait_group 0;" ::: "memory")

__device__ __forceinline__ void ldsm4(uint32_t* r, uint32_t addr) {
    asm volatile("ldmatrix.sync.aligned.m8n8.x4.shared.b16 {%0,%1,%2,%3}, [%4];"
                 : "=r"(r[0]), "=r"(r[1]), "=r"(r[2]), "=r"(r[3]) : "r"(addr));
}
#define MMA(d, a, b)                                                         \
    asm volatile("mma.sync.aligned.m16n8k16.row.col.f32.f16.f16.f32 "        \
        "{%0,%1,%2,%3}, {%4,%5,%6,%7}, {%8,%9}, {%0,%1,%2,%3};"              \
        : "+f"((d)[0]), "+f"((d)[1]), "+f"((d)[2]), "+f"((d)[3])             \
        : "r"((a)[0]), "r"((a)[1]), "r"((a)[2]), "r"((a)[3]),                \
          "r"((b)[0]), "r"((b)[1]))

// ---------------- prep kernels ----------------
__global__ __launch_bounds__(256)
void zero_dsum_kernel() {
    g_dsum[blockIdx.x * 256 + threadIdx.x] = 0.0f;
}

// Partial demod sums: block (b, tap); 256 threads = couts; loop over 256 ci.
__global__ __launch_bounds__(256)
void demod_partial_kernel(const float* __restrict__ style, const float* __restrict__ kern) {
    const int b = blockIdx.x, t = blockIdx.y;
    const int co = threadIdx.x;
    __shared__ float s2[CIN];
    float s = style[b * CIN + threadIdx.x] + 1.0f;
    s2[threadIdx.x] = s * s;
    __syncthreads();
    float acc = 0.0f;
    const float* kp = kern + (size_t)t * CIN * COUT + co;
    #pragma unroll 8
    for (int ci = 0; ci < CIN; ++ci) {
        float k = kp[(size_t)ci * COUT];
        acc += s2[ci] * k * k;
    }
    atomicAdd(&g_dsum[b * COUT + co], acc);
}

// W[t][ci][co] fp32 -> W[t][co][ci] fp16, tiled transpose (coalesced both sides)
__global__ __launch_bounds__(256)
void wprep_kernel(const float* __restrict__ kern) {
    __shared__ float tile[32][33];
    const int t   = blockIdx.x;
    const int co0 = blockIdx.y * 32;
    const int ci0 = blockIdx.z * 32;
    const int tx = threadIdx.x & 31, ty = threadIdx.x >> 5;   // 32 x 8
    #pragma unroll
    for (int r = 0; r < 4; ++r) {
        int ci = ci0 + ty + r * 8;
        tile[ty + r * 8][tx] = kern[((size_t)t * CIN + ci) * COUT + co0 + tx];
    }
    __syncthreads();
    #pragma unroll
    for (int r = 0; r < 4; ++r) {
        int co = co0 + ty + r * 8;
        g_w_h[((size_t)t * COUT + co) * CIN + ci0 + tx] =
            __float2half_rn(tile[tx][ty + r * 8]);
    }
}

// x * (style+1) -> fp16
__global__ __launch_bounds__(256)
void xprep_kernel(const float* __restrict__ x, const float* __restrict__ style) {
    __shared__ float sm[CIN];
    int b = blockIdx.y;
    sm[threadIdx.x] = style[b * CIN + threadIdx.x] + 1.0f;
    __syncthreads();
    int i = blockIdx.x * 256 + threadIdx.x;
    size_t base = (size_t)b * (HH * WW * CIN) + (size_t)i * 4;
    float4 v = *(const float4*)(x + base);
    int ci = (i * 4) & 255;
    v.x *= sm[ci]; v.y *= sm[ci + 1]; v.z *= sm[ci + 2]; v.w *= sm[ci + 3];
    __half h0 = __float2half_rn(v.x), h1 = __float2half_rn(v.y),
           h2 = __float2half_rn(v.z), h3 = __float2half_rn(v.w);
    ushort4 hv;
    hv.x = *(unsigned short*)&h0; hv.y = *(unsigned short*)&h1;
    hv.z = *(unsigned short*)&h2; hv.w = *(unsigned short*)&h3;
    *(ushort4*)(g_xm + base) = hv;
}

// ---------------- main HMMA kernel ----------------
// CTA: 128 pixels (2 rows) x 128 couts. K = 9 taps x 4 chunks of 64 ci = 36 stages.
// Stage: A 16K | B 16K = 32KB. 3-stage ring, load 2 ahead, 1 sync per stage.
// 96KB smem/CTA -> 2 CTAs/SM.
#define ST_A  0
#define ST_B  16384
#define ST_SZ 32768
#define NSTG  3
#define SMEM_TOTAL (NSTG * ST_SZ)

struct Frag { uint32_t r[4]; };

__global__ __launch_bounds__(256, 2)
void modconv_hmma_kernel(float* __restrict__ out) {
    extern __shared__ __align__(1024) char smem[];
    const uint32_t sb = smem_u32(smem);
    const int tid = threadIdx.x;
    const int wid = tid >> 5;
    const int lid = tid & 31;

    const int mtile = blockIdx.x;            // 0..511
    const int b  = mtile >> 5;
    const int y0 = (mtile & 31) * 2;
    const int n0 = blockIdx.y * 128;

    const int warp_m = wid & 1;              // 2 x 64 rows
    const int warp_n = wid >> 1;             // 4 x 32 couts

    const __half* xm = g_xm + (size_t)b * (HH * WW * CIN);

    float acc[4][4][4];
    #pragma unroll
    for (int mi = 0; mi < 4; ++mi)
        #pragma unroll
        for (int g = 0; g < 4; ++g)
            #pragma unroll
            for (int q = 0; q < 4; ++q) acc[mi][g][q] = 0.0f;

    auto load_stage = [&](int s, int buf) {
        const int t  = s >> 2;
        const int c0 = (s & 3) * 64;
        const int dy = t / 3 - 1;
        const int dx = t % 3 - 1;
        const uint32_t stage = sb + buf * ST_SZ;
        const __half* wb = g_w_h + (size_t)t * COUT * CIN;

        #pragma unroll
        for (int i = 0; i < 4; ++i) {
            int u   = tid + i * 256;          // 0..1023
            int p   = u >> 3;
            int seg = u & 7;
            int gy  = y0 + (p >> 6) + dy;
            int gx  = (p & 63) + dx;
            bool ok = ((unsigned)gy < (unsigned)HH) && ((unsigned)gx < (unsigned)WW);
            int cy = ok ? gy : 0, cx = ok ? gx : 0;
            size_t go = ((size_t)(cy * WW + cx)) * CIN + c0 + seg * 8;
            uint32_t sw = sw128((uint32_t)(p * 128 + seg * 16));
            cp16(stage + ST_A + sw, xm + go, ok ? 16u : 0u);
        }
        #pragma unroll
        for (int i = 0; i < 4; ++i) {
            int u   = tid + i * 256;
            int co  = u >> 3;
            int seg = u & 7;
            size_t go = (size_t)(n0 + co) * CIN + c0 + seg * 8;
            uint32_t sw = sw128((uint32_t)(co * 128 + seg * 16));
            cp16(stage + ST_B + sw, wb + go, 16u);
        }
    };

    // ldmatrix lane addressing
    const int a_row_base = warp_m * 64 + (lid & 15);               // + mi*16
    const int a_col_half = (lid >> 4) << 3;                        // + kk*16
    const int b_row_base = warp_n * 32 + ((lid >> 4) << 3) + (lid & 7);  // + h*16
    const int b_col_half = ((lid >> 3) & 1) << 3;

    load_stage(0, 0); CP_COMMIT();
    load_stage(1, 1); CP_COMMIT();

    int cur = 0, nxt = 2;                    // buffer of stage s, buffer for s+2
    #pragma unroll 1
    for (int s = 0; s < 36; ++s) {
        if (s < 35) CP_WAIT1(); else CP_WAIT0();
        __syncthreads();                     // stage s ready; stage s-1 (buffer nxt) consumed
        if (s + 2 < 36) { load_stage(s + 2, nxt); CP_COMMIT(); }

        const uint32_t stg = sb + cur * ST_SZ;
        #pragma unroll
        for (int kk = 0; kk < 4; ++kk) {
            Frag ah[4];
            #pragma unroll
            for (int mi = 0; mi < 4; ++mi) {
                uint32_t off = (uint32_t)((a_row_base + mi * 16) * 128 +
                                          (kk * 16 + a_col_half) * 2);
                ldsm4(ah[mi].r, stg + ST_A + sw128(off));
            }
            uint32_t bf[4][2];
            #pragma unroll
            for (int h = 0; h < 2; ++h) {
                uint32_t off = (uint32_t)((b_row_base + h * 16) * 128 +
                                          (kk * 16) * 2 + b_col_half * 2);
                uint32_t r[4];
                ldsm4(r, stg + ST_B + sw128(off));
                bf[h * 2][0] = r[0]; bf[h * 2][1] = r[1];
                bf[h * 2 + 1][0] = r[2]; bf[h * 2 + 1][1] = r[3];
            }
            #pragma unroll
            for (int mi = 0; mi < 4; ++mi)
                #pragma unroll
                for (int g = 0; g < 4; ++g)
                    MMA(acc[mi][g], ah[mi].r, bf[g]);
        }
        cur = (cur == 2) ? 0 : cur + 1;
        nxt = (nxt == 2) ? 0 : nxt + 1;
    }

    // ---- epilogue: demodulate (rsqrt of partial sums) + store ----
    const int qrow = lid >> 2;
    const int qcol = lid & 3;
    #pragma unroll
    for (int g = 0; g < 4; ++g) {
        int c = n0 + warp_n * 32 + g * 8 + qcol * 2;
        float dm0 = rsqrtf(g_dsum[b * COUT + c] + 1e-8f);
        float dm1 = rsqrtf(g_dsum[b * COUT + c + 1] + 1e-8f);
        #pragma unroll
        for (int mi = 0; mi < 4; ++mi) {
            int p0 = warp_m * 64 + mi * 16 + qrow;
            #pragma unroll
            for (int half = 0; half < 2; ++half) {
                int p = p0 + half * 8;
                int y = y0 + (p >> 6);
                int xq = p & 63;
                float2 v;
                v.x = acc[mi][g][half * 2 + 0] * dm0;
                v.y = acc[mi][g][half * 2 + 1] * dm1;
                *(float2*)(out + (((size_t)(b * HH + y)) * WW + xq) * COUT + c) = v;
            }
        }
    }
}

// ---------------- launch ----------------
extern "C" void kernel_launch(void* const* d_in, const int* in_sizes, int n_in,
                              void* d_out, int out_size) {
    const float* x     = (const float*)d_in[0];  // [16,64,64,256]
    const float* style = (const float*)d_in[1];  // [16,256]
    const float* kern  = (const float*)d_in[2];  // [3,3,256,256]
    float* out = (float*)d_out;                  // [16,64,64,256]

    cudaFuncSetAttribute(modconv_hmma_kernel,
                         cudaFuncAttributeMaxDynamicSharedMemorySize, SMEM_TOTAL);

    zero_dsum_kernel<<<BB, 256>>>();
    demod_partial_kernel<<<dim3(BB, 9), 256>>>(style, kern);
    wprep_kernel<<<dim3(9, COUT / 32, CIN / 32), 256>>>(kern);
    xprep_kernel<<<dim3((HH * WW * CIN) / (4 * 256), BB), 256>>>(x, style);

    modconv_hmma_kernel<<<dim3(512, 2), 256, SMEM_TOTAL>>>(out);
}